// round 1
// baseline (speedup 1.0000x reference)
#include <cuda_runtime.h>
#include <cstdint>
#include <math.h>

#define BB 8
#define NN 27380
#define PP 12000
#define POST 2000
#define NW 375            // PP/32 bit-words per row
#define NBUCK 8192

typedef unsigned int u32;
typedef unsigned long long u64;

// ---------------- scratch (device globals; no runtime allocation) ----------------
__device__ float4 g_boxes[BB * NN];          // decoded boxes, original order
__device__ u32    g_cnt[BB * NBUCK];
__device__ u32    g_start[BB * NBUCK];
__device__ u32    g_fill[BB * NBUCK];
__device__ u64    g_keys[BB * NN];           // sorted (score,idx) keys, descending
__device__ float  g_sx1[BB * PP], g_sy1[BB * PP], g_sx2[BB * PP], g_sy2[BB * PP], g_sa[BB * PP];
__device__ u32    g_mask[36000000];          // BB*PP*NW suppression bits (144 MB)
__device__ int    g_keep[BB * POST];
__device__ int    g_kc[BB];

// ---------------- kernel 0: zero histogram ----------------
__global__ void k_zero() {
    int i = blockIdx.x * blockDim.x + threadIdx.x;
    if (i < BB * NBUCK) g_cnt[i] = 0u;
}

// ---------------- kernel 1: decode boxes + bucket histogram ----------------
__global__ void k_decode(const float4* __restrict__ anchors,
                         const float4* __restrict__ deltas,
                         const float*  __restrict__ scores) {
    int i = blockIdx.x * blockDim.x + threadIdx.x;
    if (i >= BB * NN) return;
    int n = i % NN;
    float4 a = anchors[n];
    float4 d = deltas[i];

    // exact replication of reference op order (forced non-contracted f32 ops)
    float w  = __fadd_rn(__fsub_rn(a.z, a.x), 1.0f);
    float h  = __fadd_rn(__fsub_rn(a.w, a.y), 1.0f);
    float cx = __fadd_rn(a.x, __fmul_rn(0.5f, w));
    float cy = __fadd_rn(a.y, __fmul_rn(0.5f, h));
    float px = __fadd_rn(cx, __fmul_rn(w, d.x));
    float py = __fadd_rn(cy, __fmul_rn(h, d.y));
    float pw = __fmul_rn((float)exp((double)d.z), w);   // correctly-rounded f32 exp
    float ph = __fmul_rn((float)exp((double)d.w), w == w ? h : h);
    float x1 = __fsub_rn(px, __fmul_rn(0.5f, pw));
    float y1 = __fsub_rn(py, __fmul_rn(0.5f, ph));
    float x2 = __fadd_rn(px, __fmul_rn(0.5f, __fsub_rn(pw, 2.0f)));
    float y2 = __fadd_rn(py, __fmul_rn(0.5f, __fsub_rn(ph, 2.0f)));
    g_boxes[i] = make_float4(x1, y1, x2, y2);

    // histogram bucket (8192 = 2^13 -> s*8192 exact, floor monotone)
    float s = scores[i];
    int t = (int)(s * 8192.0f);
    if (t > NBUCK - 1) t = NBUCK - 1;
    int bi = (NBUCK - 1) - t;                    // bucket 0 = highest scores
    atomicAdd(&g_cnt[(i / NN) * NBUCK + bi], 1u);
}

// ---------------- kernel 2: per-batch exclusive scan over 8192 buckets ----------------
__global__ void k_scan() {
    int b = blockIdx.x, tid = threadIdx.x;
    int lane = tid & 31, wid = tid >> 5;
    __shared__ u32 wsum[32];
    int base = b * NBUCK + tid * 8;
    u32 v[8], pre[8], s = 0;
#pragma unroll
    for (int j = 0; j < 8; j++) v[j] = g_cnt[base + j];
#pragma unroll
    for (int j = 0; j < 8; j++) { pre[j] = s; s += v[j]; }
    u32 inc = s;
#pragma unroll
    for (int o = 1; o < 32; o <<= 1) { u32 t = __shfl_up_sync(~0u, inc, o); if (lane >= o) inc += t; }
    if (lane == 31) wsum[wid] = inc;
    __syncthreads();
    if (wid == 0) {
        u32 x = wsum[lane], xin = x;
#pragma unroll
        for (int o = 1; o < 32; o <<= 1) { u32 t = __shfl_up_sync(~0u, xin, o); if (lane >= o) xin += t; }
        wsum[lane] = xin - x;      // exclusive warp offsets
    }
    __syncthreads();
    u32 off = wsum[wid] + (inc - s);
#pragma unroll
    for (int j = 0; j < 8; j++) {
        u32 o = off + pre[j];
        g_start[base + j] = o;
        g_fill[base + j]  = o;
    }
}

// ---------------- kernel 3: scatter keys into buckets ----------------
__global__ void k_scatter(const float* __restrict__ scores) {
    int i = blockIdx.x * blockDim.x + threadIdx.x;
    if (i >= BB * NN) return;
    int b = i / NN, n = i % NN;
    float s = scores[i];
    int t = (int)(s * 8192.0f);
    if (t > NBUCK - 1) t = NBUCK - 1;
    int bi = (NBUCK - 1) - t;
    u32 pos = atomicAdd(&g_fill[b * NBUCK + bi], 1u);
    u64 key = ((u64)__float_as_uint(s) << 32) | (u64)(0xFFFFFFFFu - (u32)n);
    g_keys[(size_t)b * NN + pos] = key;
}

// ---------------- kernel 4: per-bucket insertion sort (descending) ----------------
__global__ void k_bsort() {
    int i = blockIdx.x * blockDim.x + threadIdx.x;
    if (i >= BB * NBUCK) return;
    int b = i / NBUCK, bi = i % NBUCK;
    int s = (int)g_start[b * NBUCK + bi];
    int e = (bi == NBUCK - 1) ? NN : (int)g_start[b * NBUCK + bi + 1];
    u64* keys = &g_keys[(size_t)b * NN];
    for (int p = s + 1; p < e; p++) {
        u64 k = keys[p];
        int j = p - 1;
        while (j >= s && keys[j] < k) { keys[j + 1] = keys[j]; j--; }
        keys[j + 1] = k;
    }
}

// ---------------- kernel 5: gather top-P sorted boxes (SoA) + areas ----------------
__global__ void k_gather() {
    int i = blockIdx.x * blockDim.x + threadIdx.x;
    if (i >= BB * PP) return;
    int b = i / PP, p = i % PP;
    u64 k = g_keys[(size_t)b * NN + p];
    u32 n = 0xFFFFFFFFu - (u32)(k & 0xFFFFFFFFull);
    float4 bx = g_boxes[b * NN + n];
    g_sx1[i] = bx.x; g_sy1[i] = bx.y; g_sx2[i] = bx.z; g_sy2[i] = bx.w;
    g_sa[i] = __fmul_rn(__fadd_rn(__fsub_rn(bx.z, bx.x), 1.0f),
                        __fadd_rn(__fsub_rn(bx.w, bx.y), 1.0f));
}

// ---------------- kernel 6: suppression bitmask (upper triangle) ----------------
// block: 256 thr = 8 warps. words [w0,w0+32) (lane -> word), rows [r0,r0+64) (8 per warp).
__global__ void k_mask() {
    const int b  = blockIdx.z;
    const int w0 = blockIdx.x * 32;
    const int r0 = blockIdx.y * 64;
    if (w0 + 31 < (r0 >> 5)) return;                  // fully lower-triangle -> never read

    __shared__ float sx1[1024], sy1[1024], sx2[1024], sy2[1024], sa[1024];
    const int tid = threadIdx.x, lane = tid & 31, wi = tid >> 5;
    const int cbase = w0 * 32;
    for (int i = tid; i < 1024; i += 256) {
        int c = cbase + i;
        float x1 = 0.f, y1 = 0.f, x2 = -10.f, y2 = -10.f, a = 1.f;
        if (c < PP) {
            int g = b * PP + c;
            x1 = g_sx1[g]; y1 = g_sy1[g]; x2 = g_sx2[g]; y2 = g_sy2[g]; a = g_sa[g];
        }
        int sw = (i & 31) * 32 + (i >> 5);            // swizzle: conflict-free lane access
        sx1[sw] = x1; sy1[sw] = y1; sx2[sw] = x2; sy2[sw] = y2; sa[sw] = a;
    }
    __syncthreads();

    const int w = w0 + lane;
    const int rbeg = r0 + wi * 8;
    float rx1[8], ry1[8], rx2[8], ry2[8], ra[8];
#pragma unroll
    for (int rr = 0; rr < 8; rr++) {
        int row = rbeg + rr;
        if (row < PP) {
            int g = b * PP + row;
            rx1[rr] = g_sx1[g]; ry1[rr] = g_sy1[g];
            rx2[rr] = g_sx2[g]; ry2[rr] = g_sy2[g]; ra[rr] = g_sa[g];
        } else { rx1[rr] = 0.f; ry1[rr] = 0.f; rx2[rr] = -10.f; ry2[rr] = -10.f; ra[rr] = 1.f; }
    }
    u32 acc[8] = {0, 0, 0, 0, 0, 0, 0, 0};

#pragma unroll 4
    for (int t = 0; t < 32; t++) {
        int si = t * 32 + lane;
        float cx1 = sx1[si], cy1 = sy1[si], cx2 = sx2[si], cy2 = sy2[si], ca = sa[si];
#pragma unroll
        for (int rr = 0; rr < 8; rr++) {
            float xx1 = fmaxf(rx1[rr], cx1);
            float yy1 = fmaxf(ry1[rr], cy1);
            float xx2 = fminf(rx2[rr], cx2);
            float yy2 = fminf(ry2[rr], cy2);
            float ww = fmaxf(__fadd_rn(__fsub_rn(xx2, xx1), 1.0f), 0.0f);
            float hh = fmaxf(__fadd_rn(__fsub_rn(yy2, yy1), 1.0f), 0.0f);
            float inter = __fmul_rn(ww, hh);
            float denom = __fsub_rn(__fadd_rn(ra[rr], ca), inter);
            float diff  = inter - 0.7f * denom;
            float band  = 2e-6f * denom;
            u32 bit;
            if (diff > band)        bit = 1u;
            else if (diff < -band)  bit = 0u;
            else bit = (__fdiv_rn(inter, denom) > 0.7f) ? 1u : 0u;   // exact, rare
            acc[rr] |= bit << t;
        }
    }

    if (w < NW) {
#pragma unroll
        for (int rr = 0; rr < 8; rr++) {
            int row = rbeg + rr;
            if (row >= PP) continue;
            int g = row >> 5;
            if (w < g) continue;                      // never read
            u32 word = acc[rr];
            if (w == g) word &= ~((2u << (row & 31)) - 1u);   // keep j > i only
            g_mask[((size_t)(b * PP + row)) * NW + w] = word;
        }
    }
}

// ---------------- kernel 7: serial greedy sweep (one block per batch) ----------------
__global__ void k_sweep() {
    const int b = blockIdx.x, tid = threadIdx.x;
    __shared__ u32 removed[NW];
    __shared__ u32 diag[32];
    __shared__ u32 s_kept;
    __shared__ int s_kc;
    for (int i = tid; i < NW; i += blockDim.x) removed[i] = 0u;
    if (tid == 0) s_kc = 0;
    __syncthreads();

    for (int g = 0; g < NW; g++) {
        if (tid < 32) diag[tid] = g_mask[((size_t)(b * PP + g * 32 + tid)) * NW + g];
        __syncthreads();
        if (tid == 0) {
            u32 r = removed[g];
            u32 kept = 0u;
            int cnt = s_kc;
#pragma unroll
            for (int l = 0; l < 32; l++) {
                if (cnt < POST && !((r >> l) & 1u)) {
                    kept |= 1u << l;
                    g_keep[b * POST + cnt] = g * 32 + l;
                    cnt++;
                    r |= diag[l];                      // suppress within group
                }
            }
            s_kept = kept;
            s_kc = cnt;
        }
        __syncthreads();
        if (s_kc >= POST) break;
        u32 kept = s_kept;
        if (kept) {
            for (int w = g + 1 + tid; w < NW; w += blockDim.x) {
                u32 acc = removed[w];
                u32 kb = kept;
                while (kb) {
                    int l = __ffs(kb) - 1;
                    kb &= kb - 1;
                    acc |= g_mask[((size_t)(b * PP + g * 32 + l)) * NW + w];
                }
                removed[w] = acc;
            }
        }
        __syncthreads();
    }
    if (tid == 0) g_kc[b] = s_kc;
}

// ---------------- kernel 8: write ROIs ----------------
__global__ void k_out(float* __restrict__ out) {
    int i = blockIdx.x * blockDim.x + threadIdx.x;
    if (i >= BB * POST) return;
    int b = i / POST, k = i % POST;
    float v0 = 0.f, v1 = 0.f, v2 = 0.f, v3 = 0.f, v4 = 0.f;
    if (k < g_kc[b]) {
        int pos = g_keep[b * POST + k];
        int g = b * PP + pos;
        v0 = (float)b;
        v1 = g_sx1[g]; v2 = g_sy1[g]; v3 = g_sx2[g]; v4 = g_sy2[g];
    }
    out[i * 5 + 0] = v0;
    out[i * 5 + 1] = v1;
    out[i * 5 + 2] = v2;
    out[i * 5 + 3] = v3;
    out[i * 5 + 4] = v4;
}

// ---------------- launcher ----------------
extern "C" void kernel_launch(void* const* d_in, const int* in_sizes, int n_in,
                              void* d_out, int out_size) {
    const float4* anchors = (const float4*)d_in[0];
    const float4* deltas  = (const float4*)d_in[1];
    const float*  scores  = (const float*)d_in[2];
    float* out = (float*)d_out;

    k_zero<<<(BB * NBUCK + 1023) / 1024, 1024>>>();
    k_decode<<<(BB * NN + 255) / 256, 256>>>(anchors, deltas, scores);
    k_scan<<<BB, 1024>>>();
    k_scatter<<<(BB * NN + 255) / 256, 256>>>(scores);
    k_bsort<<<(BB * NBUCK + 255) / 256, 256>>>();
    k_gather<<<(BB * PP + 255) / 256, 256>>>();
    dim3 mg(12, 188, BB);
    k_mask<<<mg, 256>>>();
    k_sweep<<<BB, 256>>>();
    k_out<<<(BB * POST + 255) / 256, 256>>>(out);
}

// round 2
// speedup vs baseline: 2.0948x; 2.0948x over previous
#include <cuda_runtime.h>
#include <cstdint>
#include <math.h>

#define BB 8
#define NN 27380
#define PP 12000
#define POST 2000
#define NW 375            // PP/32 bit-words per row (logical)
#define NWP 384           // padded row stride in words (1536B, 128B-aligned)
#define NBUCK 8192

typedef unsigned int u32;
typedef unsigned long long u64;

// ---------------- scratch (device globals; no runtime allocation) ----------------
__device__ float4 g_boxes[BB * NN];          // decoded boxes, original order
__device__ u32    g_cnt[BB * NBUCK];
__device__ u32    g_start[BB * NBUCK];
__device__ u32    g_fill[BB * NBUCK];
__device__ u64    g_keys[BB * NN];           // sorted (score,idx) keys, descending
__device__ float  g_sx1[BB * PP], g_sy1[BB * PP], g_sx2[BB * PP], g_sy2[BB * PP], g_sa[BB * PP];
__device__ u32    g_mask[BB * PP * NWP];     // suppression bits (147 MB)

// ---------------- kernel 0: zero histogram ----------------
__global__ void k_zero() {
    int i = blockIdx.x * blockDim.x + threadIdx.x;
    if (i < BB * NBUCK) g_cnt[i] = 0u;
}

// ---------------- kernel 1: decode boxes + bucket histogram ----------------
__global__ void k_decode(const float4* __restrict__ anchors,
                         const float4* __restrict__ deltas,
                         const float*  __restrict__ scores) {
    int i = blockIdx.x * blockDim.x + threadIdx.x;
    if (i >= BB * NN) return;
    int n = i % NN;
    float4 a = anchors[n];
    float4 d = deltas[i];

    // exact replication of reference op order (forced non-contracted f32 ops)
    float w  = __fadd_rn(__fsub_rn(a.z, a.x), 1.0f);
    float h  = __fadd_rn(__fsub_rn(a.w, a.y), 1.0f);
    float cx = __fadd_rn(a.x, __fmul_rn(0.5f, w));
    float cy = __fadd_rn(a.y, __fmul_rn(0.5f, h));
    float px = __fadd_rn(cx, __fmul_rn(w, d.x));
    float py = __fadd_rn(cy, __fmul_rn(h, d.y));
    float pw = __fmul_rn((float)exp((double)d.z), w);   // correctly-rounded f32 exp
    float ph = __fmul_rn((float)exp((double)d.w), h);
    float x1 = __fsub_rn(px, __fmul_rn(0.5f, pw));
    float y1 = __fsub_rn(py, __fmul_rn(0.5f, ph));
    float x2 = __fadd_rn(px, __fmul_rn(0.5f, __fsub_rn(pw, 2.0f)));
    float y2 = __fadd_rn(py, __fmul_rn(0.5f, __fsub_rn(ph, 2.0f)));
    g_boxes[i] = make_float4(x1, y1, x2, y2);

    // histogram bucket (8192 = 2^13 -> s*8192 exact, floor monotone)
    float s = scores[i];
    int t = (int)(s * 8192.0f);
    if (t > NBUCK - 1) t = NBUCK - 1;
    int bi = (NBUCK - 1) - t;                    // bucket 0 = highest scores
    atomicAdd(&g_cnt[(i / NN) * NBUCK + bi], 1u);
}

// ---------------- kernel 2: per-batch exclusive scan over 8192 buckets ----------------
__global__ void k_scan() {
    int b = blockIdx.x, tid = threadIdx.x;
    int lane = tid & 31, wid = tid >> 5;
    __shared__ u32 wsum[32];
    int base = b * NBUCK + tid * 8;
    u32 v[8], pre[8], s = 0;
#pragma unroll
    for (int j = 0; j < 8; j++) v[j] = g_cnt[base + j];
#pragma unroll
    for (int j = 0; j < 8; j++) { pre[j] = s; s += v[j]; }
    u32 inc = s;
#pragma unroll
    for (int o = 1; o < 32; o <<= 1) { u32 t = __shfl_up_sync(~0u, inc, o); if (lane >= o) inc += t; }
    if (lane == 31) wsum[wid] = inc;
    __syncthreads();
    if (wid == 0) {
        u32 x = wsum[lane], xin = x;
#pragma unroll
        for (int o = 1; o < 32; o <<= 1) { u32 t = __shfl_up_sync(~0u, xin, o); if (lane >= o) xin += t; }
        wsum[lane] = xin - x;      // exclusive warp offsets
    }
    __syncthreads();
    u32 off = wsum[wid] + (inc - s);
#pragma unroll
    for (int j = 0; j < 8; j++) {
        u32 o = off + pre[j];
        g_start[base + j] = o;
        g_fill[base + j]  = o;
    }
}

// ---------------- kernel 3: scatter keys into buckets ----------------
__global__ void k_scatter(const float* __restrict__ scores) {
    int i = blockIdx.x * blockDim.x + threadIdx.x;
    if (i >= BB * NN) return;
    int b = i / NN, n = i % NN;
    float s = scores[i];
    int t = (int)(s * 8192.0f);
    if (t > NBUCK - 1) t = NBUCK - 1;
    int bi = (NBUCK - 1) - t;
    u32 pos = atomicAdd(&g_fill[b * NBUCK + bi], 1u);
    u64 key = ((u64)__float_as_uint(s) << 32) | (u64)(0xFFFFFFFFu - (u32)n);
    g_keys[(size_t)b * NN + pos] = key;
}

// ---------------- kernel 4: per-bucket insertion sort (descending) ----------------
__global__ void k_bsort() {
    int i = blockIdx.x * blockDim.x + threadIdx.x;
    if (i >= BB * NBUCK) return;
    int b = i / NBUCK, bi = i % NBUCK;
    int s = (int)g_start[b * NBUCK + bi];
    int e = (bi == NBUCK - 1) ? NN : (int)g_start[b * NBUCK + bi + 1];
    u64* keys = &g_keys[(size_t)b * NN];
    for (int p = s + 1; p < e; p++) {
        u64 k = keys[p];
        int j = p - 1;
        while (j >= s && keys[j] < k) { keys[j + 1] = keys[j]; j--; }
        keys[j + 1] = k;
    }
}

// ---------------- kernel 5: gather top-P sorted boxes (SoA) + areas ----------------
__global__ void k_gather() {
    int i = blockIdx.x * blockDim.x + threadIdx.x;
    if (i >= BB * PP) return;
    int b = i / PP, p = i % PP;
    u64 k = g_keys[(size_t)b * NN + p];
    u32 n = 0xFFFFFFFFu - (u32)(k & 0xFFFFFFFFull);
    float4 bx = g_boxes[b * NN + n];
    g_sx1[i] = bx.x; g_sy1[i] = bx.y; g_sx2[i] = bx.z; g_sy2[i] = bx.w;
    g_sa[i] = __fmul_rn(__fadd_rn(__fsub_rn(bx.z, bx.x), 1.0f),
                        __fadd_rn(__fsub_rn(bx.w, bx.y), 1.0f));
}

// exact test: rn(inter/denom) > 0.7f  <=>  inter*2^25 >= 23488103*denom (real),
// both products exact in double (<= 49-bit significands).
__device__ __forceinline__ bool iou_exact(float inter, float denom) {
    return ((double)inter * 33554432.0) >= (23488103.0 * (double)denom);
}

// ---------------- kernel 6: suppression bitmask (upper triangle) ----------------
// block: 256 thr = 8 warps. words [w0,w0+32) (lane -> word), rows [r0,r0+64) (8 per warp).
__global__ void k_mask() {
    const int b  = blockIdx.z;
    const int w0 = blockIdx.x * 32;
    const int r0 = blockIdx.y * 64;
    if (w0 + 31 < (r0 >> 5)) return;                  // fully lower-triangle -> never read

    // physical layout: logical column i stored at (i%32)*32 + i/32  (conflict-free reads)
    __shared__ float sx1[1024], sy1[1024], sx2p[1024], sy2p[1024], sa[1024];
    const int tid = threadIdx.x, lane = tid & 31, wi = tid >> 5;
    const int cbase = w0 * 32;
    for (int i = tid; i < 1024; i += 256) {
        int c = cbase + i;
        float x1 = 0.f, y1 = 0.f, x2 = -10.f, y2 = -10.f, a = 1.f;
        if (c < PP) {
            int g = b * PP + c;
            x1 = g_sx1[g]; y1 = g_sy1[g]; x2 = g_sx2[g]; y2 = g_sy2[g]; a = g_sa[g];
        }
        int sw = (i & 31) * 32 + (i >> 5);
        sx1[sw] = x1; sy1[sw] = y1;
        sx2p[sw] = __fadd_rn(x2, 1.0f);               // pre-add +1 (exact: min(a+1,b+1)=min(a,b)+1)
        sy2p[sw] = __fadd_rn(y2, 1.0f);
        sa[sw] = a;
    }
    __syncthreads();

    const int w = w0 + lane;
    const int rbeg = r0 + wi * 8;
    float rx1[8], ry1[8], rx2p[8], ry2p[8], ra[8];
#pragma unroll
    for (int rr = 0; rr < 8; rr++) {
        int row = rbeg + rr;
        if (row < PP) {
            int g = b * PP + row;
            rx1[rr] = g_sx1[g]; ry1[rr] = g_sy1[g];
            rx2p[rr] = __fadd_rn(g_sx2[g], 1.0f);
            ry2p[rr] = __fadd_rn(g_sy2[g], 1.0f);
            ra[rr] = g_sa[g];
        } else { rx1[rr] = 0.f; ry1[rr] = 0.f; rx2p[rr] = -9.f; ry2p[rr] = -9.f; ra[rr] = 1.f; }
    }
    u32 acc[8] = {0,0,0,0,0,0,0,0};
    u32 rar[8] = {0,0,0,0,0,0,0,0};

#pragma unroll 4
    for (int t = 0; t < 32; t++) {
        int si = t * 32 + lane;                        // physical addr of column (w*32+t)
        float cx1 = sx1[si], cy1 = sy1[si], cx2p = sx2p[si], cy2p = sy2p[si], ca = sa[si];
#pragma unroll
        for (int rr = 0; rr < 8; rr++) {
            float xx1 = fmaxf(rx1[rr], cx1);
            float yy1 = fmaxf(ry1[rr], cy1);
            float ww  = fmaxf(__fsub_rn(fminf(rx2p[rr], cx2p), xx1), 0.0f);
            float hh  = fmaxf(__fsub_rn(fminf(ry2p[rr], cy2p), yy1), 0.0f);
            float inter = __fmul_rn(ww, hh);
            float denom = __fsub_rn(__fadd_rn(ra[rr], ca), inter);
            float diff  = __fmaf_rn(-0.7f, denom, inter);
            float band  = __fmul_rn(2e-6f, denom);
            acc[rr] |= (diff > band)          ? (1u << t) : 0u;
            rar[rr] |= (fabsf(diff) <= band)  ? (1u << t) : 0u;
        }
    }

    // rare exact fixup (handful of pairs chip-wide)
    u32 any = rar[0]|rar[1]|rar[2]|rar[3]|rar[4]|rar[5]|rar[6]|rar[7];
    if (any) {
#pragma unroll
        for (int rr = 0; rr < 8; rr++) {
            u32 m = rar[rr];
            while (m) {
                int t = __ffs(m) - 1; m &= m - 1;
                int si = t * 32 + lane;
                float cx1 = sx1[si], cy1 = sy1[si], cx2p = sx2p[si], cy2p = sy2p[si], ca = sa[si];
                float xx1 = fmaxf(rx1[rr], cx1);
                float yy1 = fmaxf(ry1[rr], cy1);
                float ww  = fmaxf(__fsub_rn(fminf(rx2p[rr], cx2p), xx1), 0.0f);
                float hh  = fmaxf(__fsub_rn(fminf(ry2p[rr], cy2p), yy1), 0.0f);
                float inter = __fmul_rn(ww, hh);
                float denom = __fsub_rn(__fadd_rn(ra[rr], ca), inter);
                if (iou_exact(inter, denom)) acc[rr] |= (1u << t);
            }
        }
    }

    if (w < NW) {
#pragma unroll
        for (int rr = 0; rr < 8; rr++) {
            int row = rbeg + rr;
            if (row >= PP) continue;
            int g = row >> 5;
            if (w < g) continue;                      // never read
            u32 word = acc[rr];
            if (w == g) word &= ~((2u << (row & 31)) - 1u);   // keep j > i only
            g_mask[((size_t)(b * PP + row)) * NWP + w] = word;
        }
    }
}

// ---------------- kernel 7: greedy sweep + output (one block per batch) ----------------
// 384 threads; thread tid owns mask word w=tid in a REGISTER. Kept-row ORs are
// batched 8-wide (index-clamped; OR idempotent) for MLP=8. Diag words for the
// next group are prefetched by warp 1 while thread 0 does serial selection.
__global__ void __launch_bounds__(384, 1) k_sweep(float* __restrict__ out) {
    const int b = blockIdx.x, tid = threadIdx.x;
    const int myw = tid;
    __shared__ u32 s_diag[2][32];
    __shared__ int s_klist[32];
    __shared__ int s_keep[POST];
    __shared__ u32 s_remg;
    __shared__ int s_kc, s_tot;

    u32 r = 0;
    if (tid < 32) s_diag[0][tid] = g_mask[(size_t)(b * PP + tid) * NWP];
    if (tid == 0) { s_remg = 0u; s_tot = 0; }
    __syncthreads();

    for (int g = 0; g < NW; g++) {
        // -------- phase A: serial selection (thread 0) + diag prefetch (warp 1)
        if (tid == 0) {
            u32 rem = s_remg;
            int cnt = s_tot, kc = 0;
            const u32* dg = s_diag[g & 1];
#pragma unroll 4
            for (int l = 0; l < 32; l++) {
                if (cnt < POST && !((rem >> l) & 1u)) {
                    s_keep[cnt] = g * 32 + l;
                    s_klist[kc++] = l;
                    cnt++;
                    rem |= dg[l];
                }
            }
            s_kc = kc; s_tot = cnt;
        } else if (tid >= 32 && tid < 64 && g + 1 < NW) {
            int l = tid - 32;
            s_diag[(g + 1) & 1][l] = g_mask[(size_t)(b * PP + (g + 1) * 32 + l) * NWP + (g + 1)];
        }
        __syncthreads();
        if (s_tot >= POST) break;
        int kc = s_kc;

        // -------- phase B: OR kept rows into register-resident removed words
        if (myw > g && myw < NW) {
            if (kc > 0) {
                const u32* base = g_mask + (size_t)(b * PP + g * 32) * NWP + myw;
                u32 acc = r;
                for (int j = 0; j < kc; j += 8) {
                    u32 m[8];
#pragma unroll
                    for (int q = 0; q < 8; q++) {
                        int idx = j + q; idx = idx < kc ? idx : kc - 1;
                        m[q] = base[(size_t)s_klist[idx] * NWP];
                    }
#pragma unroll
                    for (int q = 0; q < 8; q++) acc |= m[q];
                }
                r = acc;
            }
            if (myw == g + 1) s_remg = r;   // publish removed word for next group
        }
        __syncthreads();
    }

    __syncthreads();
    // -------- output: [POST,5] rows for this batch
    const int tot = s_tot;
    for (int i = tid; i < POST; i += blockDim.x) {
        float v0 = 0.f, v1 = 0.f, v2 = 0.f, v3 = 0.f, v4 = 0.f;
        if (i < tot) {
            int pos = s_keep[i];
            int gx = b * PP + pos;
            v0 = (float)b;
            v1 = g_sx1[gx]; v2 = g_sy1[gx]; v3 = g_sx2[gx]; v4 = g_sy2[gx];
        }
        float* o = out + (size_t)(b * POST + i) * 5;
        o[0] = v0; o[1] = v1; o[2] = v2; o[3] = v3; o[4] = v4;
    }
}

// ---------------- launcher ----------------
extern "C" void kernel_launch(void* const* d_in, const int* in_sizes, int n_in,
                              void* d_out, int out_size) {
    const float4* anchors = (const float4*)d_in[0];
    const float4* deltas  = (const float4*)d_in[1];
    const float*  scores  = (const float*)d_in[2];
    float* out = (float*)d_out;

    k_zero<<<(BB * NBUCK + 1023) / 1024, 1024>>>();
    k_decode<<<(BB * NN + 255) / 256, 256>>>(anchors, deltas, scores);
    k_scan<<<BB, 1024>>>();
    k_scatter<<<(BB * NN + 255) / 256, 256>>>(scores);
    k_bsort<<<(BB * NBUCK + 255) / 256, 256>>>();
    k_gather<<<(BB * PP + 255) / 256, 256>>>();
    dim3 mg(12, 188, BB);
    k_mask<<<mg, 256>>>();
    k_sweep<<<BB, 384>>>(out);
}

// round 3
// speedup vs baseline: 2.3375x; 1.1158x over previous
#include <cuda_runtime.h>
#include <cstdint>
#include <math.h>

#define BB 8
#define NN 27380
#define PP 12000
#define POST 2000
#define NW 375            // PP/32 bit-words per row (logical)
#define NWP 384           // padded row stride in words
#define GROUPS 375        // PP/32 row-groups
#define PB (GROUPS * NWP * 32)   // per-batch mask words (group-tiled layout)
#define NBUCK 8192

typedef unsigned int u32;
typedef unsigned long long u64;

// ---------------- scratch (device globals; no runtime allocation) ----------------
__device__ float4 g_boxes[BB * NN];
__device__ u32    g_cnt[BB * NBUCK];
__device__ u32    g_start[BB * NBUCK];
__device__ u32    g_fill[BB * NBUCK];
__device__ u64    g_keys[BB * NN];
__device__ float  g_sx1[BB * PP], g_sy1[BB * PP], g_sx2[BB * PP], g_sy2[BB * PP], g_sa[BB * PP];
// group-tiled mask: word for (row, w) at  b*PB + ((row>>5)*NWP + w)*32 + (row&31)
__device__ u32    g_mask[BB * PB];           // 147.5 MB

// ---------------- kernel 0: zero histogram ----------------
__global__ void k_zero() {
    int i = blockIdx.x * blockDim.x + threadIdx.x;
    if (i < BB * NBUCK) g_cnt[i] = 0u;
}

// ---------------- kernel 1: decode boxes + bucket histogram ----------------
__global__ void k_decode(const float4* __restrict__ anchors,
                         const float4* __restrict__ deltas,
                         const float*  __restrict__ scores) {
    int i = blockIdx.x * blockDim.x + threadIdx.x;
    if (i >= BB * NN) return;
    int n = i % NN;
    float4 a = anchors[n];
    float4 d = deltas[i];

    float w  = __fadd_rn(__fsub_rn(a.z, a.x), 1.0f);
    float h  = __fadd_rn(__fsub_rn(a.w, a.y), 1.0f);
    float cx = __fadd_rn(a.x, __fmul_rn(0.5f, w));
    float cy = __fadd_rn(a.y, __fmul_rn(0.5f, h));
    float px = __fadd_rn(cx, __fmul_rn(w, d.x));
    float py = __fadd_rn(cy, __fmul_rn(h, d.y));
    float pw = __fmul_rn((float)exp((double)d.z), w);
    float ph = __fmul_rn((float)exp((double)d.w), h);
    float x1 = __fsub_rn(px, __fmul_rn(0.5f, pw));
    float y1 = __fsub_rn(py, __fmul_rn(0.5f, ph));
    float x2 = __fadd_rn(px, __fmul_rn(0.5f, __fsub_rn(pw, 2.0f)));
    float y2 = __fadd_rn(py, __fmul_rn(0.5f, __fsub_rn(ph, 2.0f)));
    g_boxes[i] = make_float4(x1, y1, x2, y2);

    float s = scores[i];
    int t = (int)(s * 8192.0f);
    if (t > NBUCK - 1) t = NBUCK - 1;
    int bi = (NBUCK - 1) - t;
    atomicAdd(&g_cnt[(i / NN) * NBUCK + bi], 1u);
}

// ---------------- kernel 2: per-batch exclusive scan over 8192 buckets ----------------
__global__ void k_scan() {
    int b = blockIdx.x, tid = threadIdx.x;
    int lane = tid & 31, wid = tid >> 5;
    __shared__ u32 wsum[32];
    int base = b * NBUCK + tid * 8;
    u32 v[8], pre[8], s = 0;
#pragma unroll
    for (int j = 0; j < 8; j++) v[j] = g_cnt[base + j];
#pragma unroll
    for (int j = 0; j < 8; j++) { pre[j] = s; s += v[j]; }
    u32 inc = s;
#pragma unroll
    for (int o = 1; o < 32; o <<= 1) { u32 t = __shfl_up_sync(~0u, inc, o); if (lane >= o) inc += t; }
    if (lane == 31) wsum[wid] = inc;
    __syncthreads();
    if (wid == 0) {
        u32 x = wsum[lane], xin = x;
#pragma unroll
        for (int o = 1; o < 32; o <<= 1) { u32 t = __shfl_up_sync(~0u, xin, o); if (lane >= o) xin += t; }
        wsum[lane] = xin - x;
    }
    __syncthreads();
    u32 off = wsum[wid] + (inc - s);
#pragma unroll
    for (int j = 0; j < 8; j++) {
        u32 o = off + pre[j];
        g_start[base + j] = o;
        g_fill[base + j]  = o;
    }
}

// ---------------- kernel 3: scatter keys into buckets ----------------
__global__ void k_scatter(const float* __restrict__ scores) {
    int i = blockIdx.x * blockDim.x + threadIdx.x;
    if (i >= BB * NN) return;
    int b = i / NN, n = i % NN;
    float s = scores[i];
    int t = (int)(s * 8192.0f);
    if (t > NBUCK - 1) t = NBUCK - 1;
    int bi = (NBUCK - 1) - t;
    u32 pos = atomicAdd(&g_fill[b * NBUCK + bi], 1u);
    u64 key = ((u64)__float_as_uint(s) << 32) | (u64)(0xFFFFFFFFu - (u32)n);
    g_keys[(size_t)b * NN + pos] = key;
}

// ---------------- kernel 4: per-bucket insertion sort (descending) ----------------
__global__ void k_bsort() {
    int i = blockIdx.x * blockDim.x + threadIdx.x;
    if (i >= BB * NBUCK) return;
    int b = i / NBUCK, bi = i % NBUCK;
    int s = (int)g_start[b * NBUCK + bi];
    int e = (bi == NBUCK - 1) ? NN : (int)g_start[b * NBUCK + bi + 1];
    u64* keys = &g_keys[(size_t)b * NN];
    for (int p = s + 1; p < e; p++) {
        u64 k = keys[p];
        int j = p - 1;
        while (j >= s && keys[j] < k) { keys[j + 1] = keys[j]; j--; }
        keys[j + 1] = k;
    }
}

// ---------------- kernel 5: gather top-P sorted boxes (SoA) + areas ----------------
__global__ void k_gather() {
    int i = blockIdx.x * blockDim.x + threadIdx.x;
    if (i >= BB * PP) return;
    int b = i / PP, p = i % PP;
    u64 k = g_keys[(size_t)b * NN + p];
    u32 n = 0xFFFFFFFFu - (u32)(k & 0xFFFFFFFFull);
    float4 bx = g_boxes[b * NN + n];
    g_sx1[i] = bx.x; g_sy1[i] = bx.y; g_sx2[i] = bx.z; g_sy2[i] = bx.w;
    g_sa[i] = __fmul_rn(__fadd_rn(__fsub_rn(bx.z, bx.x), 1.0f),
                        __fadd_rn(__fsub_rn(bx.w, bx.y), 1.0f));
}

// exact test: rn(inter/denom) > 0.7f  <=>  inter*2^25 >= 23488103*denom
__device__ __forceinline__ bool iou_exact(float inter, float denom) {
    return ((double)inter * 33554432.0) >= (23488103.0 * (double)denom);
}

// ---------------- kernel 6: suppression bitmask, group-tiled output ----------------
__global__ void k_mask() {
    const int b  = blockIdx.z;
    const int w0 = blockIdx.x * 32;
    const int r0 = blockIdx.y * 64;
    const int gr0 = r0 >> 5;
    if (w0 + 31 < gr0) return;                        // fully lower-triangle

    __shared__ float sx1[1024], sy1[1024], sx2p[1024], sy2p[1024], sa[1024];
    __shared__ u32 stage[2048];
    const int tid = threadIdx.x, lane = tid & 31, wi = tid >> 5;
    const int cbase = w0 * 32;
    for (int i = tid; i < 1024; i += 256) {
        int c = cbase + i;
        float x1 = 0.f, y1 = 0.f, x2 = -10.f, y2 = -10.f, a = 1.f;
        if (c < PP) {
            int g = b * PP + c;
            x1 = g_sx1[g]; y1 = g_sy1[g]; x2 = g_sx2[g]; y2 = g_sy2[g]; a = g_sa[g];
        }
        int sw = (i & 31) * 32 + (i >> 5);
        sx1[sw] = x1; sy1[sw] = y1;
        sx2p[sw] = __fadd_rn(x2, 1.0f);
        sy2p[sw] = __fadd_rn(y2, 1.0f);
        sa[sw] = a;
    }
    __syncthreads();

    const int w = w0 + lane;
    const int rbeg = r0 + wi * 8;
    float rx1[8], ry1[8], rx2p[8], ry2p[8], ra[8];
#pragma unroll
    for (int rr = 0; rr < 8; rr++) {
        int row = rbeg + rr;
        if (row < PP) {
            int g = b * PP + row;
            rx1[rr] = g_sx1[g]; ry1[rr] = g_sy1[g];
            rx2p[rr] = __fadd_rn(g_sx2[g], 1.0f);
            ry2p[rr] = __fadd_rn(g_sy2[g], 1.0f);
            ra[rr] = g_sa[g];
        } else { rx1[rr] = 0.f; ry1[rr] = 0.f; rx2p[rr] = -9.f; ry2p[rr] = -9.f; ra[rr] = 1.f; }
    }
    u32 acc[8] = {0,0,0,0,0,0,0,0};
    u32 rar[8] = {0,0,0,0,0,0,0,0};

#pragma unroll 4
    for (int t = 0; t < 32; t++) {
        int si = t * 32 + lane;
        float cx1 = sx1[si], cy1 = sy1[si], cx2p = sx2p[si], cy2p = sy2p[si], ca = sa[si];
#pragma unroll
        for (int rr = 0; rr < 8; rr++) {
            float xx1 = fmaxf(rx1[rr], cx1);
            float yy1 = fmaxf(ry1[rr], cy1);
            float ww  = fmaxf(__fsub_rn(fminf(rx2p[rr], cx2p), xx1), 0.0f);
            float hh  = fmaxf(__fsub_rn(fminf(ry2p[rr], cy2p), yy1), 0.0f);
            float inter = __fmul_rn(ww, hh);
            float denom = __fsub_rn(__fadd_rn(ra[rr], ca), inter);
            float diff  = __fmaf_rn(-0.7f, denom, inter);
            float band  = __fmul_rn(2e-6f, denom);
            acc[rr] |= (diff > band)          ? (1u << t) : 0u;
            rar[rr] |= (fabsf(diff) <= band)  ? (1u << t) : 0u;
        }
    }

    u32 any = rar[0]|rar[1]|rar[2]|rar[3]|rar[4]|rar[5]|rar[6]|rar[7];
    if (any) {
#pragma unroll
        for (int rr = 0; rr < 8; rr++) {
            u32 m = rar[rr];
            while (m) {
                int t = __ffs(m) - 1; m &= m - 1;
                int si = t * 32 + lane;
                float cx1 = sx1[si], cy1 = sy1[si], cx2p = sx2p[si], cy2p = sy2p[si], ca = sa[si];
                float xx1 = fmaxf(rx1[rr], cx1);
                float yy1 = fmaxf(ry1[rr], cy1);
                float ww  = fmaxf(__fsub_rn(fminf(rx2p[rr], cx2p), xx1), 0.0f);
                float hh  = fmaxf(__fsub_rn(fminf(ry2p[rr], cy2p), yy1), 0.0f);
                float inter = __fmul_rn(ww, hh);
                float denom = __fsub_rn(__fadd_rn(ra[rr], ca), inter);
                if (iou_exact(inter, denom)) acc[rr] |= (1u << t);
            }
        }
    }

    // stage (XOR-swizzled) then coalesced group-tiled store
#pragma unroll
    for (int rr = 0; rr < 8; rr++) {
        int rl = wi * 8 + rr;                 // local row 0..63
        int row = r0 + rl;
        int gi = rl >> 5, l = rl & 31;
        u32 word = acc[rr];
        if (w == (row >> 5)) word &= ~((2u << (row & 31)) - 1u);  // keep j > i
        stage[gi * 1024 + lane * 32 + ((l ^ lane) & 31)] = word;
    }
    __syncthreads();

#pragma unroll
    for (int gi = 0; gi < 2; gi++) {
        int gr = gr0 + gi;
        if (gr >= GROUPS) continue;
        size_t obase = (size_t)b * PB + ((size_t)gr * NWP + w0) * 32;
#pragma unroll
        for (int rep = 0; rep < 4; rep++) {
            int j = rep * 256 + tid;
            int wl = j >> 5, l = j & 31;
            if (w0 + wl < gr) continue;               // lower triangle, never read
            g_mask[obase + (size_t)wl * 32 + l] = stage[gi * 1024 + wl * 32 + ((l ^ wl) & 31)];
        }
    }
}

// ---------------- kernel 7: greedy sweep + output (one block per batch) ----------------
// Thread myw owns removed-word myw in a register; per group it holds the whole
// 32-row tile (column myw) in registers, prefetched one group ahead (8x LDG.128,
// coalesced). Selection = ffs loop over staged diag words in smem.
__global__ void __launch_bounds__(384, 1) k_sweep(float* __restrict__ out) {
    const int b = blockIdx.x, tid = threadIdx.x;
    const int myw = tid;
    const size_t mb = (size_t)b * PB;
    __shared__ u32 s_diag[32];
    __shared__ int s_keep[POST];
    __shared__ u32 s_k32;
    __shared__ int s_tot;

    u32 r = 0;
    u32 cur[32], nxt[32];
    {
        const uint4* p = reinterpret_cast<const uint4*>(&g_mask[mb + (size_t)myw * 32]);
#pragma unroll
        for (int i = 0; i < 8; i++) {
            uint4 v = p[i];
            cur[4*i] = v.x; cur[4*i+1] = v.y; cur[4*i+2] = v.z; cur[4*i+3] = v.w;
        }
    }
    if (tid == 0) s_tot = 0;
    __syncthreads();

    for (int g = 0; g < NW; g++) {
        // prefetch next group tile (consumed after end-of-loop barrier)
        if (myw > g && g + 1 < NW) {
            const uint4* p = reinterpret_cast<const uint4*>(
                &g_mask[mb + ((size_t)(g + 1) * NWP + myw) * 32]);
#pragma unroll
            for (int i = 0; i < 8; i++) {
                uint4 v = p[i];
                nxt[4*i] = v.x; nxt[4*i+1] = v.y; nxt[4*i+2] = v.z; nxt[4*i+3] = v.w;
            }
        }
        // selection by the diagonal owner
        if (myw == g) {
#pragma unroll
            for (int l = 0; l < 32; l++) s_diag[l] = cur[l];
            u32 rem = r;
            int cnt = s_tot;
            u32 kept = 0u;
            u32 cand = ~rem;
            while (cand && cnt < POST) {
                int l = __ffs(cand) - 1;
                kept |= 1u << l;
                s_keep[cnt++] = g * 32 + l;
                rem |= s_diag[l];
                cand &= ~rem & ~((2u << l) - 1u);
            }
            s_k32 = kept;
            s_tot = cnt;
        }
        __syncthreads();
        if (s_tot >= POST) break;
        u32 k32 = s_k32;
        if (myw > g) {
            if (k32) {
#pragma unroll
                for (int l = 0; l < 32; l++) r |= ((k32 >> l) & 1u) ? cur[l] : 0u;
            }
#pragma unroll
            for (int l = 0; l < 32; l++) cur[l] = nxt[l];
        }
        __syncthreads();
    }

    __syncthreads();
    const int tot = s_tot;
    for (int i = tid; i < POST; i += blockDim.x) {
        float v0 = 0.f, v1 = 0.f, v2 = 0.f, v3 = 0.f, v4 = 0.f;
        if (i < tot) {
            int pos = s_keep[i];
            int gx = b * PP + pos;
            v0 = (float)b;
            v1 = g_sx1[gx]; v2 = g_sy1[gx]; v3 = g_sx2[gx]; v4 = g_sy2[gx];
        }
        float* o = out + (size_t)(b * POST + i) * 5;
        o[0] = v0; o[1] = v1; o[2] = v2; o[3] = v3; o[4] = v4;
    }
}

// ---------------- launcher ----------------
extern "C" void kernel_launch(void* const* d_in, const int* in_sizes, int n_in,
                              void* d_out, int out_size) {
    const float4* anchors = (const float4*)d_in[0];
    const float4* deltas  = (const float4*)d_in[1];
    const float*  scores  = (const float*)d_in[2];
    float* out = (float*)d_out;

    k_zero<<<(BB * NBUCK + 1023) / 1024, 1024>>>();
    k_decode<<<(BB * NN + 255) / 256, 256>>>(anchors, deltas, scores);
    k_scan<<<BB, 1024>>>();
    k_scatter<<<(BB * NN + 255) / 256, 256>>>(scores);
    k_bsort<<<(BB * NBUCK + 255) / 256, 256>>>();
    k_gather<<<(BB * PP + 255) / 256, 256>>>();
    dim3 mg(12, 188, BB);
    k_mask<<<mg, 256>>>();
    k_sweep<<<BB, 384>>>(out);
}